// round 16
// baseline (speedup 1.0000x reference)
#include <cuda_runtime.h>
#include <cstdint>
#include <math.h>

#define HH 64
#define WW 64
#define NPIX 4096
#define NA 9
#define NANCH 36864
#define NSORT 65536
#define KPRE 2000
#define KPOST 256
#define NCLS 21
#define NO 105
#define NOP 112
#define KDIM 50176
#define KSPLIT 112
#define KRANGE 448
#define PARTSTRIDE (KPOST * NOP)
#define NWU 65536
#define NWR (56 * 256)
#define NTILE 1024
#define VPLANE (256 * NTILE)

// output layout (flat concat, tuple order)
#define OUT_CLS0 0
#define OUT_TFM0 73728
#define OUT_PROP 221184
#define OUT_FBOX 222464
#define OUT_FCLS 223744
#define OUT_FTFM 229120

typedef unsigned int u32;
typedef unsigned long long u64;

__device__ __forceinline__ u64 u64mn(u64 x, u64 y) { return x < y ? x : y; }
__device__ __forceinline__ u64 u64mx(u64 x, u64 y) { return x > y ? x : y; }

// ---------------- scratch (static device globals; no allocation) ----------
__device__ float g_h[256 * NPIX];                       // conv output (4 MB)
__device__ float g_U[16 * NWU];                         // winograd weights [k][ic][oc] (4 MB)
__device__ float g_V[16 * VPLANE];                      // transformed input (16.8 MB)
__device__ float g_M[16 * VPLANE];                      // gemm output (16.8 MB)
__device__ float g_wrpn[NWR];                           // cls/tfm weights [o][c]
__device__ float g_bx[NANCH], g_by[NANCH], g_bw[NANCH], g_bh[NANCH];
__device__ u64 g_key[NSORT];
__device__ u64 g_key2[32768];
__device__ float4 g_box4[KPRE];                         // x1,y1,x2,y2
__device__ float g_area[KPRE];
__device__ float g_tx[KPRE], g_ty[KPRE], g_tw[KPRE], g_th[KPRE];
__device__ u32 g_mask[2048 * 64];                       // NMS suppression bitmask
__device__ float g_rois[KPOST * 4];
__device__ float g_feats[KPOST * KDIM];                 // 51 MB
__device__ float g_part[KSPLIT * PARTSTRIDE];           // 12.8 MB

// ---------------- K0: prep (winograd weight transform + pack cls/tfm) -------
__global__ void k_prep(const float* __restrict__ w,
                       const float* __restrict__ cls_w, const float* __restrict__ tfm_w) {
    int idx = blockIdx.x * 1024 + threadIdx.x;
    if (idx < NWU) {
        int ic = idx >> 8, oc = idx & 255;
        const float* gp = w + oc * 2304 + ic * 9;
        float g0[3] = {gp[0], gp[1], gp[2]};
        float g1[3] = {gp[3], gp[4], gp[5]};
        float g2[3] = {gp[6], gp[7], gp[8]};
        float u[4][3];
#pragma unroll
        for (int c = 0; c < 3; c++) {
            u[0][c] = g0[c];
            u[1][c] = 0.5f * (g0[c] + g1[c] + g2[c]);
            u[2][c] = 0.5f * (g0[c] - g1[c] + g2[c]);
            u[3][c] = g2[c];
        }
#pragma unroll
        for (int r = 0; r < 4; r++) {
            float U0 = u[r][0];
            float U1 = 0.5f * (u[r][0] + u[r][1] + u[r][2]);
            float U2 = 0.5f * (u[r][0] - u[r][1] + u[r][2]);
            float U3 = u[r][2];
            g_U[(r * 4 + 0) * NWU + ic * 256 + oc] = U0;
            g_U[(r * 4 + 1) * NWU + ic * 256 + oc] = U1;
            g_U[(r * 4 + 2) * NWU + ic * 256 + oc] = U2;
            g_U[(r * 4 + 3) * NWU + ic * 256 + oc] = U3;
        }
    } else if (idx < NWU + NWR) {
        int j = idx - NWU;
        int c = j & 255, o = j >> 8;
        float v = 0.f;
        if (o < 18) v = cls_w[o * 256 + c];
        else if (o < 54) v = tfm_w[(o - 18) * 256 + c];
        g_wrpn[j] = v;
    }
}

// ---------------- K1a: winograd input transform -----------------------------
__global__ void k_wino_in(const float* __restrict__ x) {
    int gid = blockIdx.x * 256 + threadIdx.x;   // 262144 threads
    int ic = gid >> 10, tile = gid & 1023;
    int ty = tile >> 5, tx = tile & 31;
    int r0 = 2 * ty - 1, c0 = 2 * tx - 1;
    const float* xb = x + ic * NPIX;
    float d[4][4];
#pragma unroll
    for (int r = 0; r < 4; r++) {
        int rr = r0 + r;
        bool rok = (rr >= 0 && rr < HH);
#pragma unroll
        for (int c = 0; c < 4; c++) {
            int cc = c0 + c;
            d[r][c] = (rok && cc >= 0 && cc < WW) ? xb[rr * WW + cc] : 0.f;
        }
    }
    float t[4][4];
#pragma unroll
    for (int j = 0; j < 4; j++) {
        t[0][j] = d[0][j] - d[2][j];
        t[1][j] = d[1][j] + d[2][j];
        t[2][j] = d[2][j] - d[1][j];
        t[3][j] = d[1][j] - d[3][j];
    }
#pragma unroll
    for (int i = 0; i < 4; i++) {
        float V0 = t[i][0] - t[i][2];
        float V1 = t[i][1] + t[i][2];
        float V2 = t[i][2] - t[i][1];
        float V3 = t[i][1] - t[i][3];
        g_V[(i * 4 + 0) * VPLANE + ic * NTILE + tile] = V0;
        g_V[(i * 4 + 1) * VPLANE + ic * NTILE + tile] = V1;
        g_V[(i * 4 + 2) * VPLANE + ic * NTILE + tile] = V2;
        g_V[(i * 4 + 3) * VPLANE + ic * NTILE + tile] = V3;
    }
}

// ---------------- K1b: 16 batched GEMMs M[k] = U[k] x V[k] ------------------
__global__ void k_wino_gemm() {
    __shared__ float Us[16][64];
    __shared__ float Vs[16][128];
    int tid = threadIdx.x;
    int t0 = blockIdx.x * 128, oc0 = blockIdx.y * 64, k = blockIdx.z;
    int og = tid & 15, tg = tid >> 4;
    int oc4 = og * 4, t8 = tg * 8;
    const float* Ubase = g_U + k * NWU + oc0;
    const float* Vbase = g_V + k * VPLANE + t0;
    float acc[4][8] = {};
    for (int ic0 = 0; ic0 < 256; ic0 += 16) {
        for (int i = tid; i < 1024; i += 256) {
            int r = i >> 6, c = i & 63;
            Us[r][c] = Ubase[(ic0 + r) * 256 + c];
        }
        for (int i = tid; i < 512; i += 256) {
            int r = i >> 5, c4 = (i & 31) * 4;
            *(float4*)&Vs[r][c4] = *(const float4*)&Vbase[(ic0 + r) * NTILE + c4];
        }
        __syncthreads();
#pragma unroll
        for (int kk = 0; kk < 16; kk++) {
            float4 u = *(const float4*)&Us[kk][oc4];
            float4 va = *(const float4*)&Vs[kk][t8];
            float4 vb = *(const float4*)&Vs[kk][t8 + 4];
            float uu[4] = {u.x, u.y, u.z, u.w};
            float vv[8] = {va.x, va.y, va.z, va.w, vb.x, vb.y, vb.z, vb.w};
#pragma unroll
            for (int q = 0; q < 4; q++)
#pragma unroll
                for (int s = 0; s < 8; s++) acc[q][s] += uu[q] * vv[s];
        }
        __syncthreads();
    }
#pragma unroll
    for (int q = 0; q < 4; q++) {
        float* dst = &g_M[k * VPLANE + (oc0 + oc4 + q) * NTILE + t0 + t8];
        *(float4*)dst = make_float4(acc[q][0], acc[q][1], acc[q][2], acc[q][3]);
        *(float4*)(dst + 4) = make_float4(acc[q][4], acc[q][5], acc[q][6], acc[q][7]);
    }
}

// ---------------- K1c: winograd output transform + bias ---------------------
__global__ void k_wino_out(const float* __restrict__ bias) {
    int gid = blockIdx.x * 256 + threadIdx.x;   // 262144 threads
    int oc = gid >> 10, tile = gid & 1023;
    int ty = tile >> 5, tx = tile & 31;
    float m[4][4];
#pragma unroll
    for (int k = 0; k < 16; k++)
        m[k >> 2][k & 3] = g_M[k * VPLANE + oc * NTILE + tile];
    float t0[4], t1[4];
#pragma unroll
    for (int j = 0; j < 4; j++) {
        t0[j] = m[0][j] + m[1][j] + m[2][j];
        t1[j] = m[1][j] - m[2][j] - m[3][j];
    }
    float b = bias[oc];
    float Y00 = t0[0] + t0[1] + t0[2] + b;
    float Y01 = t0[1] - t0[2] - t0[3] + b;
    float Y10 = t1[0] + t1[1] + t1[2] + b;
    float Y11 = t1[1] - t1[2] - t1[3] + b;
    float* hp = &g_h[oc * NPIX + (2 * ty) * WW + 2 * tx];
    *(float2*)hp = make_float2(Y00, Y01);
    *(float2*)(hp + WW) = make_float2(Y10, Y11);
}

// ---------------- K2: RPN linear heads (transposed weights, 4-c unroll) -----
__global__ void k_rpn_heads(const float* __restrict__ cls_b, const float* __restrict__ tfm_b,
                            float* __restrict__ out) {
    __shared__ float hs[32][32];           // [c][pl]
    __shared__ float wsm[56][32];          // [o][c]
    int tid = threadIdx.x;
    int lane = tid & 31, og = tid >> 5;
    int p0 = blockIdx.x * 32;
    float acc[7];
#pragma unroll
    for (int q = 0; q < 7; q++) acc[q] = 0.f;
    for (int c0 = 0; c0 < 256; c0 += 32) {
        for (int t = tid; t < 1024; t += 256) {
            int c = t >> 5, pl = t & 31;
            hs[c][pl] = g_h[(c0 + c) * NPIX + p0 + pl];
        }
        for (int t = tid; t < 1792; t += 256) {
            int o = t >> 5, c = t & 31;
            wsm[o][c] = g_wrpn[o * 256 + c0 + c];
        }
        __syncthreads();
#pragma unroll
        for (int c4 = 0; c4 < 32; c4 += 4) {
            float h0 = hs[c4 + 0][lane];
            float h1 = hs[c4 + 1][lane];
            float h2 = hs[c4 + 2][lane];
            float h3 = hs[c4 + 3][lane];
#pragma unroll
            for (int q = 0; q < 7; q++) {
                float4 wv = *(const float4*)&wsm[og * 7 + q][c4];
                acc[q] += h0 * wv.x;
                acc[q] += h1 * wv.y;
                acc[q] += h2 * wv.z;
                acc[q] += h3 * wv.w;
            }
        }
        __syncthreads();
    }
    int p = p0 + lane;
#pragma unroll
    for (int q = 0; q < 7; q++) {
        int o = og * 7 + q;
        if (o < 18)      out[OUT_CLS0 + o * NPIX + p] = acc[q] + cls_b[o];
        else if (o < 54) out[OUT_TFM0 + (o - 18) * NPIX + p] = acc[q] + tfm_b[o - 18];
    }
}

// ---------------- decode helper ---------------------------------------------
__device__ __forceinline__ u64 decode_one(const float* __restrict__ out,
                                          const float* __restrict__ anchors, int gid) {
    int a = gid >> 12;
    int p = gid & 4095;
    int i = p >> 6, j = p & 63;
    float logit = out[OUT_CLS0 + (2 * a) * NPIX + p] - out[OUT_CLS0 + (2 * a + 1) * NPIX + p];
    float obj = 1.0f / (1.0f + expf(-logit));
    float t0 = out[OUT_TFM0 + (4 * a + 0) * NPIX + p];
    float t1 = out[OUT_TFM0 + (4 * a + 1) * NPIX + p];
    float t2 = out[OUT_TFM0 + (4 * a + 2) * NPIX + p];
    float t3 = out[OUT_TFM0 + (4 * a + 3) * NPIX + p];
    float ah = anchors[a * 2 + 0], aw = anchors[a * 2 + 1];
    float bx = (float)j + aw * (t1 - 0.5f) / 16.0f;
    float by = (float)i + ah * (t0 - 0.5f) / 16.0f;
    float bw = aw / 16.0f * expf(t3);
    float bh = ah / 16.0f * expf(t2);
    bx = fminf(fmaxf(bx, 0.f), 63.f);
    by = fminf(fmaxf(by, 0.f), 63.f);
    bw = fminf(fmaxf(bx + bw, 0.f), 63.f) - bx;
    bh = fminf(fmaxf(by + bh, 0.f), 63.f) - by;
    g_bx[gid] = bx; g_by[gid] = by; g_bw[gid] = bw; g_bh[gid] = bh;
    unsigned int sb = __float_as_uint(obj);
    return ((u64)(~sb) << 32) | (unsigned int)gid;
}

// ---------------- fused decode + hybrid reg/shfl bitonic sort ---------------
__device__ __forceinline__ int SK(int i) { return i + (i >> 5); }

__global__ void k_decode_sort(const float* __restrict__ out, const float* __restrict__ anchors) {
    __shared__ u64 s[2048 + 64];
    int base = blockIdx.x * 2048;
    int tid = threadIdx.x;
    if (base >= NANCH) {
        for (int t = tid; t < 2048; t += 1024)
            g_key[base + t] = 0xFFFFFFFFFFFFFFFFull;
        return;
    }
    int L = tid & 31, W = tid >> 5;
    int iA = W * 64 + L;
    int iB = iA + 32;
    u64 a = decode_one(out, anchors, base + iA);
    u64 b = decode_one(out, anchors, base + iB);

#pragma unroll
    for (int k = 2; k <= 32; k <<= 1) {
        bool upA = ((iA & k) == 0);
        bool upB = ((iB & k) == 0);
#pragma unroll
        for (int j = 16; j >= 1; j >>= 1) {
            if (j <= (k >> 1)) {
                bool lower = ((L & j) == 0);
                u64 pa = __shfl_xor_sync(0xffffffffu, a, j);
                a = (upA == lower) ? u64mn(a, pa) : u64mx(a, pa);
                u64 pb = __shfl_xor_sync(0xffffffffu, b, j);
                b = (upB == lower) ? u64mn(b, pb) : u64mx(b, pb);
            }
        }
    }
    for (int k = 64; k <= 2048; k <<= 1) {
        bool up = ((iA & k) == 0);
        if (k >= 128) {
            s[SK(iA)] = a; s[SK(iB)] = b;
            for (int j = k >> 1; j >= 64; j >>= 1) {
                __syncthreads();
                int i = ((tid & ~(j - 1)) << 1) | (tid & (j - 1));
                int l = i | j;
                bool asc = ((i & k) == 0);
                u64 x = s[SK(i)], y = s[SK(l)];
                bool sw = asc ? (x > y) : (x < y);
                if (sw) { s[SK(i)] = y; s[SK(l)] = x; }
            }
            __syncthreads();
            a = s[SK(iA)]; b = s[SK(iB)];
        }
        {
            bool sw = up ? (a > b) : (a < b);
            if (sw) { u64 t0 = a; a = b; b = t0; }
        }
#pragma unroll
        for (int j = 16; j >= 1; j >>= 1) {
            bool lower = ((L & j) == 0);
            u64 pa = __shfl_xor_sync(0xffffffffu, a, j);
            a = (up == lower) ? u64mn(a, pa) : u64mx(a, pa);
            u64 pb = __shfl_xor_sync(0xffffffffu, b, j);
            b = (up == lower) ? u64mn(b, pb) : u64mx(b, pb);
        }
    }
    g_key[base + iA] = a;
    g_key[base + iB] = b;
}

// ---------------- 4-way top-2048 merge (two levels in one kernel) -----------
__global__ void k_merge4(int phase) {
    __shared__ u64 sm[4096 + 128];
    const u64* in = phase ? g_key2 : g_key;
    u64* outp     = phase ? g_key  : g_key2;
    const u64* A = in + (size_t)blockIdx.x * 8192;
    for (int t = threadIdx.x; t < 2048; t += 1024) {
        u64 a = A[t],        b = A[2048 + 2047 - t];
        sm[SK(t)] = a < b ? a : b;
        u64 c = A[4096 + t], d = A[6144 + 2047 - t];
        sm[SK(2048 + t)] = c < d ? c : d;
    }
    for (int j = 1024; j > 0; j >>= 1) {
        __syncthreads();
        int t = threadIdx.x;
        int i0 = ((t & ~(j - 1)) << 1) | (t & (j - 1));
        int l0 = i0 | j;
        u64 a = sm[SK(i0)], b = sm[SK(l0)];
        if (a > b) { sm[SK(i0)] = b; sm[SK(l0)] = a; }
        int i1 = 2048 + i0, l1 = 2048 + l0;
        u64 c = sm[SK(i1)], d = sm[SK(l1)];
        if (c > d) { sm[SK(i1)] = d; sm[SK(l1)] = c; }
    }
    __syncthreads();
    for (int t = threadIdx.x; t < 2048; t += 1024) {
        u64 a = sm[SK(t)], b = sm[SK(2048 + 2047 - t)];
        sm[SK(t)] = a < b ? a : b;
    }
    for (int j = 1024; j > 0; j >>= 1) {
        __syncthreads();
        int t = threadIdx.x;
        int i = ((t & ~(j - 1)) << 1) | (t & (j - 1));
        int l = i | j;
        u64 a = sm[SK(i)], b = sm[SK(l)];
        if (a > b) { sm[SK(i)] = b; sm[SK(l)] = a; }
    }
    __syncthreads();
    for (int t = threadIdx.x; t < 2048; t += 1024) outp[blockIdx.x * 2048 + t] = sm[SK(t)];
}

// ---------------- final 2-way merge (hybrid clean) + box gather -------------
__global__ void k_final_merge() {
    __shared__ u64 s[2048 + 64];
    int tid = threadIdx.x;
    int L = tid & 31, W = tid >> 5;
    int iA = W * 64 + L;
    int iB = iA + 32;
    u64 a = u64mn(g_key[iA], g_key[2048 + 2047 - iA]);
    u64 b = u64mn(g_key[iB], g_key[2048 + 2047 - iB]);
    s[SK(iA)] = a; s[SK(iB)] = b;
    for (int j = 1024; j >= 64; j >>= 1) {
        __syncthreads();
        int i = ((tid & ~(j - 1)) << 1) | (tid & (j - 1));
        int l = i | j;
        u64 x = s[SK(i)], y = s[SK(l)];
        if (x > y) { s[SK(i)] = y; s[SK(l)] = x; }
    }
    __syncthreads();
    a = s[SK(iA)]; b = s[SK(iB)];
    { if (a > b) { u64 t0 = a; a = b; b = t0; } }
#pragma unroll
    for (int j = 16; j >= 1; j >>= 1) {
        bool lower = ((L & j) == 0);
        u64 pa = __shfl_xor_sync(0xffffffffu, a, j);
        a = lower ? u64mn(a, pa) : u64mx(a, pa);
        u64 pb = __shfl_xor_sync(0xffffffffu, b, j);
        b = lower ? u64mn(b, pb) : u64mx(b, pb);
    }
    if (iA < KPRE) {
        u32 idx = (u32)(a & 0xFFFFFFFFull);
        float x1 = g_bx[idx], y1 = g_by[idx], w = g_bw[idx], h = g_bh[idx];
        g_box4[iA] = make_float4(x1, y1, x1 + w, y1 + h);
        g_area[iA] = w * h;
        g_tx[iA] = x1; g_ty[iA] = y1; g_tw[iA] = w; g_th[iA] = h;
    }
    if (iB < KPRE) {
        u32 idx = (u32)(b & 0xFFFFFFFFull);
        float x1 = g_bx[idx], y1 = g_by[idx], w = g_bw[idx], h = g_bh[idx];
        g_box4[iB] = make_float4(x1, y1, x1 + w, y1 + h);
        g_area[iB] = w * h;
        g_tx[iB] = x1; g_ty[iB] = y1; g_tw[iB] = w; g_th[iB] = h;
    }
}

// ---------------- NMS stage 1: IOU suppression bitmask ----------------------
__global__ void k_iou_build() {
    __shared__ float sx1[KPRE], sy1[KPRE], sx2[KPRE], sy2[KPRE], sar[KPRE];
    int tid = threadIdx.x;
    for (int t = tid; t < KPRE; t += 512) {
        float4 b = g_box4[t];
        sx1[t] = b.x; sy1[t] = b.y; sx2[t] = b.z; sy2[t] = b.w;
        sar[t] = g_area[t];
    }
    __syncthreads();
    int i = blockIdx.x * 16 + (tid >> 5);
    int lane = tid & 31;
    if (i >= KPRE) return;
    float x1 = sx1[i], y1 = sy1[i], x2 = sx2[i], y2 = sy2[i], ar = sar[i];
    for (int wq = 0; wq < 63; wq++) {
        u32 bits = 0;
        if ((wq + 1) * 32 > i + 1) {
            int j = wq * 32 + lane;
            bool sup = false;
            if (j < KPRE && j > i) {
                float ix = fmaxf(x1, sx1[j]);
                float iy = fmaxf(y1, sy1[j]);
                float iw = fmaxf(fminf(x2, sx2[j]) - ix, 0.f);
                float ih = fmaxf(fminf(y2, sy2[j]) - iy, 0.f);
                float inter = iw * ih;
                float iou = inter / (ar + sar[j] - inter);
                sup = iou > 0.7f;
            }
            bits = __ballot_sync(0xffffffffu, sup);
        }
        if (lane == 0) g_mask[i * 64 + wq] = bits;
    }
    if (lane == 0) g_mask[i * 64 + 63] = 0u;
}

// ---------------- NMS stage 2: chunked greedy scan + select 256 -------------
__global__ void k_nms_scan(float* __restrict__ out) {
    __shared__ u32 keep[64];
    __shared__ u64 intraS[64];
    __shared__ u64 aliveSh;
    __shared__ u32 orP[16][64];
    __shared__ int wpfx[65];
    __shared__ int selS[KPOST];
    int tid = threadIdx.x;
    if (tid < 64) keep[tid] = (tid < 62) ? 0xFFFFFFFFu : (tid == 62 ? 0xFFFFu : 0u);
    __syncthreads();
    for (int c = 0; c < 32; c++) {
        if (tid < 64) {
            u32 lo = g_mask[(c * 64 + tid) * 64 + 2 * c];
            u32 hi = g_mask[(c * 64 + tid) * 64 + 2 * c + 1];
            intraS[tid] = ((u64)hi << 32) | lo;
        }
        __syncthreads();
        if (tid == 0) {
            u64 alive = ((u64)keep[2 * c + 1] << 32) | (u64)keep[2 * c];
#pragma unroll
            for (int r = 0; r < 64; r++) {
                u64 m = intraS[r];
                if ((alive >> r) & 1ull) alive &= ~m;
            }
            aliveSh = alive;
            keep[2 * c]     = (u32)alive;
            keep[2 * c + 1] = (u32)(alive >> 32);
        }
        __syncthreads();
        u64 alive = aliveSh;
        int w = tid & 63, g = tid >> 6;
        u32 acc = 0;
#pragma unroll
        for (int q = 0; q < 4; q++) {
            int r = g * 4 + q;
            if ((alive >> r) & 1ull) acc |= g_mask[(c * 64 + r) * 64 + w];
        }
        orP[g][w] = acc;
        __syncthreads();
        if (tid < 64) {
            u32 o = 0;
#pragma unroll
            for (int g2 = 0; g2 < 16; g2++) o |= orP[g2][tid];
            keep[tid] &= ~o;
        }
        __syncthreads();
    }
    if (tid == 0) {
        int s = 0;
        for (int w = 0; w < 64; w++) { wpfx[w] = s; s += __popc(keep[w]); }
        wpfx[64] = s;
    }
    __syncthreads();
    int tot = wpfx[64];
    for (int t = tid; t < KPRE; t += 1024) {
        u32 wv = keep[t >> 5];
        int sub = t & 31;
        bool alive = (wv >> sub) & 1u;
        int rank = wpfx[t >> 5] + __popc(wv & ((1u << sub) - 1u));
        if (alive) {
            if (rank < KPOST) selS[rank] = t;
        } else {
            int slot = tot + (t - rank);
            if (slot < KPOST) selS[slot] = t;
        }
    }
    __syncthreads();
    if (tid < KPOST) {
        int r = selS[tid];
        float rx = g_tx[r], ry = g_ty[r], rw = g_tw[r], rh = g_th[r];
        g_rois[tid * 4 + 0] = rx;
        g_rois[tid * 4 + 1] = ry;
        g_rois[tid * 4 + 2] = rw;
        g_rois[tid * 4 + 3] = rh;
        out[OUT_PROP + tid * 5 + 0] = 0.f;
        out[OUT_PROP + tid * 5 + 1] = rx * 16.f;
        out[OUT_PROP + tid * 5 + 2] = ry * 16.f;
        out[OUT_PROP + tid * 5 + 3] = rw * 16.f;
        out[OUT_PROP + tid * 5 + 4] = rh * 16.f;
    }
}

// ---------------- ROI align (28x28 bilinear -> 14x14 max pool) --------------
__global__ void k_roi_align(const float* __restrict__ x) {
    __shared__ int x0s[28], y0s[28];
    __shared__ float wxs[28], wys[28];
    int roi = blockIdx.x, cg = blockIdx.y, tid = threadIdx.x;
    float rx = g_rois[roi * 4 + 0], ry = g_rois[roi * 4 + 1];
    float rw = g_rois[roi * 4 + 2], rh = g_rois[roi * 4 + 3];
    if (tid < 28) {
        float gx = rx + (((float)tid + 0.5f) * rw) / 28.0f;
        gx = fminf(fmaxf(gx, 0.f), 63.f);
        int x0 = (int)floorf(gx);
        x0 = min(max(x0, 0), 62);
        x0s[tid] = x0; wxs[tid] = gx - (float)x0;
    } else if (tid >= 32 && tid < 60) {
        int g = tid - 32;
        float gy = ry + (((float)g + 0.5f) * rh) / 28.0f;
        gy = fminf(fmaxf(gy, 0.f), 63.f);
        int y0 = (int)floorf(gy);
        y0 = min(max(y0, 0), 62);
        y0s[g] = y0; wys[g] = gy - (float)y0;
    }
    __syncthreads();
    for (int idx = tid; idx < 32 * 196; idx += 256) {
        int cl = idx / 196, pp = idx % 196, pi = pp / 14, pj = pp % 14;
        const float* base = x + (cg * 32 + cl) * NPIX;
        float m = -1e30f;
#pragma unroll
        for (int dy = 0; dy < 2; dy++) {
            int gi = 2 * pi + dy;
            int y0 = y0s[gi]; float wy = wys[gi];
#pragma unroll
            for (int dx = 0; dx < 2; dx++) {
                int gj = 2 * pj + dx;
                int x0 = x0s[gj]; float wx = wxs[gj];
                const float* p00 = base + y0 * WW + x0;
                float f00 = p00[0], f10 = p00[1], f01 = p00[WW], f11 = p00[WW + 1];
                float v = f00 * (1.f - wy) * (1.f - wx) + f01 * wy * (1.f - wx)
                        + f10 * (1.f - wy) * wx + f11 * wy * wx;
                m = fmaxf(m, v);
            }
        }
        g_feats[roi * KDIM + (cg * 32 + cl) * 196 + pp] = m;
    }
}

// ---------------- head GEMM (split-K=112, g_part layout [kz][roi][o]) -------
__global__ void k_head_gemm(const float* __restrict__ head_w) {
    __shared__ float wsm[16][NOP];
    __shared__ float fsm[16][64];
    int tid = threadIdx.x;                 // 0..223
    int mt = blockIdx.x, kz = blockIdx.y;
    int ng = tid >> 4, mg = tid & 15;
    int o0 = ng * 8;
    int r0 = mt * 64 + mg * 4;
    int K0 = kz * KRANGE;
    float acc[8][4] = {};
    for (int kc = 0; kc < KRANGE; kc += 16) {
        for (int t = tid; t < 16 * NOP; t += 224) {
            int o = t >> 4, kk = t & 15;
            wsm[kk][o] = (o < NO) ? head_w[(size_t)o * KDIM + K0 + kc + kk] : 0.f;
        }
        for (int t = tid; t < 256; t += 224) {
            int r = t >> 2;
            int kk4 = (t & 3) * 4;
            const float4 f4 = *(const float4*)(g_feats + (mt * 64 + r) * KDIM + K0 + kc + kk4);
            fsm[kk4 + 0][r] = f4.x; fsm[kk4 + 1][r] = f4.y;
            fsm[kk4 + 2][r] = f4.z; fsm[kk4 + 3][r] = f4.w;
        }
        __syncthreads();
#pragma unroll
        for (int kk = 0; kk < 16; kk++) {
            float4 wa = *(const float4*)&wsm[kk][o0];
            float4 wb = *(const float4*)&wsm[kk][o0 + 4];
            float4 f4 = *(const float4*)&fsm[kk][mg * 4];
            float wv[8] = {wa.x, wa.y, wa.z, wa.w, wb.x, wb.y, wb.z, wb.w};
            float fv[4] = {f4.x, f4.y, f4.z, f4.w};
#pragma unroll
            for (int q = 0; q < 8; q++)
#pragma unroll
                for (int s = 0; s < 4; s++) acc[q][s] += wv[q] * fv[s];
        }
        __syncthreads();
    }
#pragma unroll
    for (int s = 0; s < 4; s++) {
        float* dst = &g_part[kz * PARTSTRIDE + (r0 + s) * NOP + o0];
        float4 v1 = make_float4(acc[0][s], acc[1][s], acc[2][s], acc[3][s]);
        float4 v2 = make_float4(acc[4][s], acc[5][s], acc[6][s], acc[7][s]);
        *(float4*)dst = v1;
        *(float4*)(dst + 4) = v2;
    }
}

// ---------------- fused reduce + bias + argmax + final decode ---------------
__global__ void k_head_final(const float* __restrict__ head_b, float* __restrict__ out) {
    __shared__ float ho[NO];
    int roi = blockIdx.x;
    int tid = threadIdx.x;
    if (tid < NO) {
        float s = 0.f;
        for (int z = 0; z < KSPLIT; z++) s += g_part[z * PARTSTRIDE + roi * NOP + tid];
        s += head_b[tid];
        ho[tid] = s;
        if (tid < NCLS) out[OUT_FCLS + roi * NCLS + tid] = s;
        else            out[OUT_FTFM + roi * 84 + (tid - NCLS)] = s;
    }
    __syncthreads();
    if (tid == 0) {
        int det = 0;
        float best = ho[0];
        for (int c = 1; c < NCLS; c++) {
            float v = ho[c];
            if (v > best) { best = v; det = c; }
        }
        float t0 = ho[NCLS + det * 4 + 0];
        float t1 = ho[NCLS + det * 4 + 1];
        float t2 = ho[NCLS + det * 4 + 2];
        float t3 = ho[NCLS + det * 4 + 3];
        float X = g_rois[roi * 4 + 0] * 16.f;
        float Y = g_rois[roi * 4 + 1] * 16.f;
        float Wd = g_rois[roi * 4 + 2] * 16.f;
        float Hd = g_rois[roi * 4 + 3] * 16.f;
        out[OUT_FBOX + roi * 5 + 0] = 0.f;
        out[OUT_FBOX + roi * 5 + 1] = X + Wd * t1;
        out[OUT_FBOX + roi * 5 + 2] = Y + Hd * t0;
        out[OUT_FBOX + roi * 5 + 3] = Wd * expf(t3);
        out[OUT_FBOX + roi * 5 + 4] = Hd * expf(t2);
    }
}

// ---------------- launcher --------------------------------------------------
extern "C" void kernel_launch(void* const* d_in, const int* in_sizes, int n_in,
                              void* d_out, int out_size) {
    const float* x      = (const float*)d_in[0];
    const float* rpn_w  = (const float*)d_in[1];
    const float* rpn_b  = (const float*)d_in[2];
    const float* cls_w  = (const float*)d_in[3];
    const float* cls_b  = (const float*)d_in[4];
    const float* tfm_w  = (const float*)d_in[5];
    const float* tfm_b  = (const float*)d_in[6];
    const float* head_w = (const float*)d_in[7];
    const float* head_b = (const float*)d_in[8];
    const float* anchors = (const float*)d_in[9];
    float* out = (float*)d_out;

    k_prep<<<(NWU + NWR + 1023) / 1024, 1024>>>(rpn_w, cls_w, tfm_w);

    k_wino_in<<<1024, 256>>>(x);
    k_wino_gemm<<<dim3(8, 4, 16), 256>>>();
    k_wino_out<<<1024, 256>>>(rpn_b);

    k_rpn_heads<<<128, 256>>>(cls_b, tfm_b, out);

    k_decode_sort<<<32, 1024>>>(out, anchors);
    k_merge4<<<8, 1024>>>(0);     // g_key (32 runs) -> g_key2 (8 runs)
    k_merge4<<<2, 1024>>>(1);     // g_key2 (8 runs) -> g_key (2 runs)
    k_final_merge<<<1, 1024>>>(); // g_key (2 runs) -> boxes

    k_iou_build<<<125, 512>>>();
    k_nms_scan<<<1, 1024>>>(out);

    k_roi_align<<<dim3(KPOST, 8), 256>>>(x);
    k_head_gemm<<<dim3(4, KSPLIT), 224>>>(head_w);
    k_head_final<<<KPOST, 128>>>(head_b, out);
}

// round 17
// speedup vs baseline: 1.3151x; 1.3151x over previous
#include <cuda_runtime.h>
#include <cstdint>
#include <math.h>

#define HH 64
#define WW 64
#define NPIX 4096
#define NA 9
#define NANCH 36864
#define NSORT 65536
#define KPRE 2000
#define KPOST 256
#define NCLS 21
#define NO 105
#define NOP 112
#define KDIM 50176
#define KSPLIT 112
#define KRANGE 448
#define PARTSTRIDE (KPOST * NOP)
#define NWT (256 * 9 * 256)
#define NWR (56 * 256)

// output layout (flat concat, tuple order)
#define OUT_CLS0 0
#define OUT_TFM0 73728
#define OUT_PROP 221184
#define OUT_FBOX 222464
#define OUT_FCLS 223744
#define OUT_FTFM 229120

typedef unsigned int u32;
typedef unsigned long long u64;

__device__ __forceinline__ u64 u64mn(u64 x, u64 y) { return x < y ? x : y; }
__device__ __forceinline__ u64 u64mx(u64 x, u64 y) { return x > y ? x : y; }

// ---------------- scratch (static device globals; no allocation) ----------
__device__ float g_h[256 * NPIX];                       // conv output (4 MB)
__device__ float g_wt[NWT];                             // rpn_w transposed [ic][k][oc]
__device__ float g_wrpn[NWR];                           // cls/tfm weights [o][c]
__device__ float g_bx[NANCH], g_by[NANCH], g_bw[NANCH], g_bh[NANCH];
__device__ u64 g_key[NSORT];
__device__ u64 g_key2[32768];
__device__ float4 g_box4[KPRE];                         // x1,y1,x2,y2
__device__ float g_area[KPRE];
__device__ float g_tx[KPRE], g_ty[KPRE], g_tw[KPRE], g_th[KPRE];
__device__ u32 g_mask[2048 * 64];                       // NMS suppression bitmask
__device__ float g_rois[KPOST * 4];
__device__ float g_feats[KPOST * KDIM];                 // 51 MB
__device__ float g_part[KSPLIT * PARTSTRIDE];           // 12.8 MB

// ---------------- K0: weight prep (transpose rpn_w + pack cls/tfm [o][c]) ---
__global__ void k_prep(const float* __restrict__ w,
                       const float* __restrict__ cls_w, const float* __restrict__ tfm_w) {
    int idx = blockIdx.x * 1024 + threadIdx.x;
    if (idx < NWT) {
        int oc = idx & 255;
        int rest = idx >> 8;
        int k = rest % 9, ic = rest / 9;
        g_wt[idx] = w[oc * 2304 + ic * 9 + k];
    } else if (idx < NWT + NWR) {
        int j = idx - NWT;
        int c = j & 255, o = j >> 8;
        float v = 0.f;
        if (o < 18) v = cls_w[o * 256 + c];
        else if (o < 54) v = tfm_w[(o - 18) * 256 + c];
        g_wrpn[j] = v;
    }
}

// ---------------- K1: 3x3 conv + bias (scalar FFMA, coalesced weight fill) --
__global__ void k_conv3x3(const float* __restrict__ x,
                          const float* __restrict__ bias) {
    __shared__ float xs[16][10][20];
    __shared__ float ws[16][9][32];
    int tid = threadIdx.x;
    int pg = tid & 31, og = tid >> 5;
    int row = pg >> 2, col0 = (pg & 3) * 4;
    int ocl = og * 4;
    int bx0 = blockIdx.x * 16, by0 = blockIdx.y * 8, oc0 = blockIdx.z * 32;
    float acc[4][4] = {};
    for (int ic0 = 0; ic0 < 256; ic0 += 16) {
        for (int t = tid; t < 2880; t += 256) {
            int ii = t / 180, rr = (t / 18) % 10, cc = t % 18;
            int gy = by0 + rr - 1, gx = bx0 + cc - 1;
            float v = 0.f;
            if (gy >= 0 && gy < HH && gx >= 0 && gx < WW)
                v = x[(ic0 + ii) * NPIX + gy * WW + gx];
            xs[ii][rr][cc] = v;
        }
        for (int t = tid; t < 1152; t += 256) {
            int o4 = t & 7;
            int k = (t >> 3) % 9;
            int ii = t / 72;
            *(float4*)&ws[ii][k][o4 * 4] =
                *(const float4*)&g_wt[((ic0 + ii) * 9 + k) * 256 + oc0 + o4 * 4];
        }
        __syncthreads();
        for (int ii = 0; ii < 16; ii++) {
#pragma unroll
            for (int ky = 0; ky < 3; ky++) {
                float4 v0 = *(const float4*)&xs[ii][row + ky][col0];
                float2 v4 = *(const float2*)&xs[ii][row + ky][col0 + 4];
                float xr[6] = {v0.x, v0.y, v0.z, v0.w, v4.x, v4.y};
#pragma unroll
                for (int kx = 0; kx < 3; kx++) {
                    float4 wv4 = *(const float4*)&ws[ii][ky * 3 + kx][ocl];
                    float wvv[4] = {wv4.x, wv4.y, wv4.z, wv4.w};
#pragma unroll
                    for (int o = 0; o < 4; o++) {
                        acc[o][0] += xr[kx + 0] * wvv[o];
                        acc[o][1] += xr[kx + 1] * wvv[o];
                        acc[o][2] += xr[kx + 2] * wvv[o];
                        acc[o][3] += xr[kx + 3] * wvv[o];
                    }
                }
            }
        }
        __syncthreads();
    }
    int py = by0 + row, px = bx0 + col0;
#pragma unroll
    for (int o = 0; o < 4; o++) {
        int oc = oc0 + ocl + o;
        float b = bias[oc];
        float4 v;
        v.x = acc[o][0] + b; v.y = acc[o][1] + b;
        v.z = acc[o][2] + b; v.w = acc[o][3] + b;
        *(float4*)&g_h[oc * NPIX + py * WW + px] = v;
    }
}

// ---------------- K2: RPN linear heads (transposed weights, 4-c unroll) -----
__global__ void k_rpn_heads(const float* __restrict__ cls_b, const float* __restrict__ tfm_b,
                            float* __restrict__ out) {
    __shared__ float hs[32][32];           // [c][pl]
    __shared__ float wsm[56][32];          // [o][c]
    int tid = threadIdx.x;
    int lane = tid & 31, og = tid >> 5;
    int p0 = blockIdx.x * 32;
    float acc[7];
#pragma unroll
    for (int q = 0; q < 7; q++) acc[q] = 0.f;
    for (int c0 = 0; c0 < 256; c0 += 32) {
        for (int t = tid; t < 1024; t += 256) {
            int c = t >> 5, pl = t & 31;
            hs[c][pl] = g_h[(c0 + c) * NPIX + p0 + pl];
        }
        for (int t = tid; t < 1792; t += 256) {
            int o = t >> 5, c = t & 31;
            wsm[o][c] = g_wrpn[o * 256 + c0 + c];
        }
        __syncthreads();
#pragma unroll
        for (int c4 = 0; c4 < 32; c4 += 4) {
            float h0 = hs[c4 + 0][lane];
            float h1 = hs[c4 + 1][lane];
            float h2 = hs[c4 + 2][lane];
            float h3 = hs[c4 + 3][lane];
#pragma unroll
            for (int q = 0; q < 7; q++) {
                float4 wv = *(const float4*)&wsm[og * 7 + q][c4];
                acc[q] += h0 * wv.x;
                acc[q] += h1 * wv.y;
                acc[q] += h2 * wv.z;
                acc[q] += h3 * wv.w;
            }
        }
        __syncthreads();
    }
    int p = p0 + lane;
#pragma unroll
    for (int q = 0; q < 7; q++) {
        int o = og * 7 + q;
        if (o < 18)      out[OUT_CLS0 + o * NPIX + p] = acc[q] + cls_b[o];
        else if (o < 54) out[OUT_TFM0 + (o - 18) * NPIX + p] = acc[q] + tfm_b[o - 18];
    }
}

// ---------------- decode helper ---------------------------------------------
__device__ __forceinline__ u64 decode_one(const float* __restrict__ out,
                                          const float* __restrict__ anchors, int gid) {
    int a = gid >> 12;
    int p = gid & 4095;
    int i = p >> 6, j = p & 63;
    float logit = out[OUT_CLS0 + (2 * a) * NPIX + p] - out[OUT_CLS0 + (2 * a + 1) * NPIX + p];
    float obj = 1.0f / (1.0f + expf(-logit));
    float t0 = out[OUT_TFM0 + (4 * a + 0) * NPIX + p];
    float t1 = out[OUT_TFM0 + (4 * a + 1) * NPIX + p];
    float t2 = out[OUT_TFM0 + (4 * a + 2) * NPIX + p];
    float t3 = out[OUT_TFM0 + (4 * a + 3) * NPIX + p];
    float ah = anchors[a * 2 + 0], aw = anchors[a * 2 + 1];
    float bx = (float)j + aw * (t1 - 0.5f) / 16.0f;
    float by = (float)i + ah * (t0 - 0.5f) / 16.0f;
    float bw = aw / 16.0f * expf(t3);
    float bh = ah / 16.0f * expf(t2);
    bx = fminf(fmaxf(bx, 0.f), 63.f);
    by = fminf(fmaxf(by, 0.f), 63.f);
    bw = fminf(fmaxf(bx + bw, 0.f), 63.f) - bx;
    bh = fminf(fmaxf(by + bh, 0.f), 63.f) - by;
    g_bx[gid] = bx; g_by[gid] = by; g_bw[gid] = bw; g_bh[gid] = bh;
    unsigned int sb = __float_as_uint(obj);
    return ((u64)(~sb) << 32) | (unsigned int)gid;
}

// ---------------- fused decode + hybrid reg/shfl bitonic sort ---------------
__device__ __forceinline__ int SK(int i) { return i + (i >> 5); }

__global__ void k_decode_sort(const float* __restrict__ out, const float* __restrict__ anchors) {
    __shared__ u64 s[2048 + 64];
    int base = blockIdx.x * 2048;
    int tid = threadIdx.x;
    if (base >= NANCH) {
        for (int t = tid; t < 2048; t += 1024)
            g_key[base + t] = 0xFFFFFFFFFFFFFFFFull;
        return;
    }
    int L = tid & 31, W = tid >> 5;
    int iA = W * 64 + L;
    int iB = iA + 32;
    u64 a = decode_one(out, anchors, base + iA);
    u64 b = decode_one(out, anchors, base + iB);

#pragma unroll
    for (int k = 2; k <= 32; k <<= 1) {
        bool upA = ((iA & k) == 0);
        bool upB = ((iB & k) == 0);
#pragma unroll
        for (int j = 16; j >= 1; j >>= 1) {
            if (j <= (k >> 1)) {
                bool lower = ((L & j) == 0);
                u64 pa = __shfl_xor_sync(0xffffffffu, a, j);
                a = (upA == lower) ? u64mn(a, pa) : u64mx(a, pa);
                u64 pb = __shfl_xor_sync(0xffffffffu, b, j);
                b = (upB == lower) ? u64mn(b, pb) : u64mx(b, pb);
            }
        }
    }
    for (int k = 64; k <= 2048; k <<= 1) {
        bool up = ((iA & k) == 0);
        if (k >= 128) {
            s[SK(iA)] = a; s[SK(iB)] = b;
            for (int j = k >> 1; j >= 64; j >>= 1) {
                __syncthreads();
                int i = ((tid & ~(j - 1)) << 1) | (tid & (j - 1));
                int l = i | j;
                bool asc = ((i & k) == 0);
                u64 x = s[SK(i)], y = s[SK(l)];
                bool sw = asc ? (x > y) : (x < y);
                if (sw) { s[SK(i)] = y; s[SK(l)] = x; }
            }
            __syncthreads();
            a = s[SK(iA)]; b = s[SK(iB)];
        }
        {
            bool sw = up ? (a > b) : (a < b);
            if (sw) { u64 t0 = a; a = b; b = t0; }
        }
#pragma unroll
        for (int j = 16; j >= 1; j >>= 1) {
            bool lower = ((L & j) == 0);
            u64 pa = __shfl_xor_sync(0xffffffffu, a, j);
            a = (up == lower) ? u64mn(a, pa) : u64mx(a, pa);
            u64 pb = __shfl_xor_sync(0xffffffffu, b, j);
            b = (up == lower) ? u64mn(b, pb) : u64mx(b, pb);
        }
    }
    g_key[base + iA] = a;
    g_key[base + iB] = b;
}

// ---------------- 4-way top-2048 merge (two levels in one kernel) -----------
__global__ void k_merge4(int phase) {
    __shared__ u64 sm[4096 + 128];
    const u64* in = phase ? g_key2 : g_key;
    u64* outp     = phase ? g_key  : g_key2;
    const u64* A = in + (size_t)blockIdx.x * 8192;
    for (int t = threadIdx.x; t < 2048; t += 1024) {
        u64 a = A[t],        b = A[2048 + 2047 - t];
        sm[SK(t)] = a < b ? a : b;
        u64 c = A[4096 + t], d = A[6144 + 2047 - t];
        sm[SK(2048 + t)] = c < d ? c : d;
    }
    for (int j = 1024; j > 0; j >>= 1) {
        __syncthreads();
        int t = threadIdx.x;
        int i0 = ((t & ~(j - 1)) << 1) | (t & (j - 1));
        int l0 = i0 | j;
        u64 a = sm[SK(i0)], b = sm[SK(l0)];
        if (a > b) { sm[SK(i0)] = b; sm[SK(l0)] = a; }
        int i1 = 2048 + i0, l1 = 2048 + l0;
        u64 c = sm[SK(i1)], d = sm[SK(l1)];
        if (c > d) { sm[SK(i1)] = d; sm[SK(l1)] = c; }
    }
    __syncthreads();
    for (int t = threadIdx.x; t < 2048; t += 1024) {
        u64 a = sm[SK(t)], b = sm[SK(2048 + 2047 - t)];
        sm[SK(t)] = a < b ? a : b;
    }
    for (int j = 1024; j > 0; j >>= 1) {
        __syncthreads();
        int t = threadIdx.x;
        int i = ((t & ~(j - 1)) << 1) | (t & (j - 1));
        int l = i | j;
        u64 a = sm[SK(i)], b = sm[SK(l)];
        if (a > b) { sm[SK(i)] = b; sm[SK(l)] = a; }
    }
    __syncthreads();
    for (int t = threadIdx.x; t < 2048; t += 1024) outp[blockIdx.x * 2048 + t] = sm[SK(t)];
}

// ---------------- final 2-way merge (hybrid clean) + box gather -------------
__global__ void k_final_merge() {
    __shared__ u64 s[2048 + 64];
    int tid = threadIdx.x;
    int L = tid & 31, W = tid >> 5;
    int iA = W * 64 + L;
    int iB = iA + 32;
    u64 a = u64mn(g_key[iA], g_key[2048 + 2047 - iA]);
    u64 b = u64mn(g_key[iB], g_key[2048 + 2047 - iB]);
    s[SK(iA)] = a; s[SK(iB)] = b;
    for (int j = 1024; j >= 64; j >>= 1) {
        __syncthreads();
        int i = ((tid & ~(j - 1)) << 1) | (tid & (j - 1));
        int l = i | j;
        u64 x = s[SK(i)], y = s[SK(l)];
        if (x > y) { s[SK(i)] = y; s[SK(l)] = x; }
    }
    __syncthreads();
    a = s[SK(iA)]; b = s[SK(iB)];
    { if (a > b) { u64 t0 = a; a = b; b = t0; } }
#pragma unroll
    for (int j = 16; j >= 1; j >>= 1) {
        bool lower = ((L & j) == 0);
        u64 pa = __shfl_xor_sync(0xffffffffu, a, j);
        a = lower ? u64mn(a, pa) : u64mx(a, pa);
        u64 pb = __shfl_xor_sync(0xffffffffu, b, j);
        b = lower ? u64mn(b, pb) : u64mx(b, pb);
    }
    if (iA < KPRE) {
        u32 idx = (u32)(a & 0xFFFFFFFFull);
        float x1 = g_bx[idx], y1 = g_by[idx], w = g_bw[idx], h = g_bh[idx];
        g_box4[iA] = make_float4(x1, y1, x1 + w, y1 + h);
        g_area[iA] = w * h;
        g_tx[iA] = x1; g_ty[iA] = y1; g_tw[iA] = w; g_th[iA] = h;
    }
    if (iB < KPRE) {
        u32 idx = (u32)(b & 0xFFFFFFFFull);
        float x1 = g_bx[idx], y1 = g_by[idx], w = g_bw[idx], h = g_bh[idx];
        g_box4[iB] = make_float4(x1, y1, x1 + w, y1 + h);
        g_area[iB] = w * h;
        g_tx[iB] = x1; g_ty[iB] = y1; g_tw[iB] = w; g_th[iB] = h;
    }
}

// ---------------- NMS stage 1: IOU suppression bitmask ----------------------
__global__ void k_iou_build() {
    __shared__ float sx1[KPRE], sy1[KPRE], sx2[KPRE], sy2[KPRE], sar[KPRE];
    int tid = threadIdx.x;
    for (int t = tid; t < KPRE; t += 512) {
        float4 b = g_box4[t];
        sx1[t] = b.x; sy1[t] = b.y; sx2[t] = b.z; sy2[t] = b.w;
        sar[t] = g_area[t];
    }
    __syncthreads();
    int i = blockIdx.x * 16 + (tid >> 5);
    int lane = tid & 31;
    if (i >= KPRE) return;
    float x1 = sx1[i], y1 = sy1[i], x2 = sx2[i], y2 = sy2[i], ar = sar[i];
    for (int wq = 0; wq < 63; wq++) {
        u32 bits = 0;
        if ((wq + 1) * 32 > i + 1) {
            int j = wq * 32 + lane;
            bool sup = false;
            if (j < KPRE && j > i) {
                float ix = fmaxf(x1, sx1[j]);
                float iy = fmaxf(y1, sy1[j]);
                float iw = fmaxf(fminf(x2, sx2[j]) - ix, 0.f);
                float ih = fmaxf(fminf(y2, sy2[j]) - iy, 0.f);
                float inter = iw * ih;
                float iou = inter / (ar + sar[j] - inter);
                sup = iou > 0.7f;
            }
            bits = __ballot_sync(0xffffffffu, sup);
        }
        if (lane == 0) g_mask[i * 64 + wq] = bits;
    }
    if (lane == 0) g_mask[i * 64 + 63] = 0u;
}

// ---------------- NMS stage 2: chunked greedy scan + select 256 -------------
__global__ void k_nms_scan(float* __restrict__ out) {
    __shared__ u32 keep[64];
    __shared__ u64 intraS[64];
    __shared__ u64 aliveSh;
    __shared__ u32 orP[16][64];
    __shared__ int wpfx[65];
    __shared__ int selS[KPOST];
    int tid = threadIdx.x;
    if (tid < 64) keep[tid] = (tid < 62) ? 0xFFFFFFFFu : (tid == 62 ? 0xFFFFu : 0u);
    __syncthreads();
    for (int c = 0; c < 32; c++) {
        if (tid < 64) {
            u32 lo = g_mask[(c * 64 + tid) * 64 + 2 * c];
            u32 hi = g_mask[(c * 64 + tid) * 64 + 2 * c + 1];
            intraS[tid] = ((u64)hi << 32) | lo;
        }
        __syncthreads();
        if (tid == 0) {
            u64 alive = ((u64)keep[2 * c + 1] << 32) | (u64)keep[2 * c];
#pragma unroll
            for (int r = 0; r < 64; r++) {
                u64 m = intraS[r];
                if ((alive >> r) & 1ull) alive &= ~m;
            }
            aliveSh = alive;
            keep[2 * c]     = (u32)alive;
            keep[2 * c + 1] = (u32)(alive >> 32);
        }
        __syncthreads();
        u64 alive = aliveSh;
        int w = tid & 63, g = tid >> 6;
        u32 acc = 0;
#pragma unroll
        for (int q = 0; q < 4; q++) {
            int r = g * 4 + q;
            if ((alive >> r) & 1ull) acc |= g_mask[(c * 64 + r) * 64 + w];
        }
        orP[g][w] = acc;
        __syncthreads();
        if (tid < 64) {
            u32 o = 0;
#pragma unroll
            for (int g2 = 0; g2 < 16; g2++) o |= orP[g2][tid];
            keep[tid] &= ~o;
        }
        __syncthreads();
    }
    if (tid == 0) {
        int s = 0;
        for (int w = 0; w < 64; w++) { wpfx[w] = s; s += __popc(keep[w]); }
        wpfx[64] = s;
    }
    __syncthreads();
    int tot = wpfx[64];
    for (int t = tid; t < KPRE; t += 1024) {
        u32 wv = keep[t >> 5];
        int sub = t & 31;
        bool alive = (wv >> sub) & 1u;
        int rank = wpfx[t >> 5] + __popc(wv & ((1u << sub) - 1u));
        if (alive) {
            if (rank < KPOST) selS[rank] = t;
        } else {
            int slot = tot + (t - rank);
            if (slot < KPOST) selS[slot] = t;
        }
    }
    __syncthreads();
    if (tid < KPOST) {
        int r = selS[tid];
        float rx = g_tx[r], ry = g_ty[r], rw = g_tw[r], rh = g_th[r];
        g_rois[tid * 4 + 0] = rx;
        g_rois[tid * 4 + 1] = ry;
        g_rois[tid * 4 + 2] = rw;
        g_rois[tid * 4 + 3] = rh;
        out[OUT_PROP + tid * 5 + 0] = 0.f;
        out[OUT_PROP + tid * 5 + 1] = rx * 16.f;
        out[OUT_PROP + tid * 5 + 2] = ry * 16.f;
        out[OUT_PROP + tid * 5 + 3] = rw * 16.f;
        out[OUT_PROP + tid * 5 + 4] = rh * 16.f;
    }
}

// ---------------- ROI align (28x28 bilinear -> 14x14 max pool) --------------
__global__ void k_roi_align(const float* __restrict__ x) {
    __shared__ int x0s[28], y0s[28];
    __shared__ float wxs[28], wys[28];
    int roi = blockIdx.x, cg = blockIdx.y, tid = threadIdx.x;
    float rx = g_rois[roi * 4 + 0], ry = g_rois[roi * 4 + 1];
    float rw = g_rois[roi * 4 + 2], rh = g_rois[roi * 4 + 3];
    if (tid < 28) {
        float gx = rx + (((float)tid + 0.5f) * rw) / 28.0f;
        gx = fminf(fmaxf(gx, 0.f), 63.f);
        int x0 = (int)floorf(gx);
        x0 = min(max(x0, 0), 62);
        x0s[tid] = x0; wxs[tid] = gx - (float)x0;
    } else if (tid >= 32 && tid < 60) {
        int g = tid - 32;
        float gy = ry + (((float)g + 0.5f) * rh) / 28.0f;
        gy = fminf(fmaxf(gy, 0.f), 63.f);
        int y0 = (int)floorf(gy);
        y0 = min(max(y0, 0), 62);
        y0s[g] = y0; wys[g] = gy - (float)y0;
    }
    __syncthreads();
    for (int idx = tid; idx < 32 * 196; idx += 256) {
        int cl = idx / 196, pp = idx % 196, pi = pp / 14, pj = pp % 14;
        const float* base = x + (cg * 32 + cl) * NPIX;
        float m = -1e30f;
#pragma unroll
        for (int dy = 0; dy < 2; dy++) {
            int gi = 2 * pi + dy;
            int y0 = y0s[gi]; float wy = wys[gi];
#pragma unroll
            for (int dx = 0; dx < 2; dx++) {
                int gj = 2 * pj + dx;
                int x0 = x0s[gj]; float wx = wxs[gj];
                const float* p00 = base + y0 * WW + x0;
                float f00 = p00[0], f10 = p00[1], f01 = p00[WW], f11 = p00[WW + 1];
                float v = f00 * (1.f - wy) * (1.f - wx) + f01 * wy * (1.f - wx)
                        + f10 * (1.f - wy) * wx + f11 * wy * wx;
                m = fmaxf(m, v);
            }
        }
        g_feats[roi * KDIM + (cg * 32 + cl) * 196 + pp] = m;
    }
}

// ---------------- head GEMM (split-K=112, g_part layout [kz][roi][o]) -------
__global__ void k_head_gemm(const float* __restrict__ head_w) {
    __shared__ float wsm[16][NOP];
    __shared__ float fsm[16][64];
    int tid = threadIdx.x;                 // 0..223
    int mt = blockIdx.x, kz = blockIdx.y;
    int ng = tid >> 4, mg = tid & 15;
    int o0 = ng * 8;
    int r0 = mt * 64 + mg * 4;
    int K0 = kz * KRANGE;
    float acc[8][4] = {};
    for (int kc = 0; kc < KRANGE; kc += 16) {
        for (int t = tid; t < 16 * NOP; t += 224) {
            int o = t >> 4, kk = t & 15;
            wsm[kk][o] = (o < NO) ? head_w[(size_t)o * KDIM + K0 + kc + kk] : 0.f;
        }
        for (int t = tid; t < 256; t += 224) {
            int r = t >> 2;
            int kk4 = (t & 3) * 4;
            const float4 f4 = *(const float4*)(g_feats + (mt * 64 + r) * KDIM + K0 + kc + kk4);
            fsm[kk4 + 0][r] = f4.x; fsm[kk4 + 1][r] = f4.y;
            fsm[kk4 + 2][r] = f4.z; fsm[kk4 + 3][r] = f4.w;
        }
        __syncthreads();
#pragma unroll
        for (int kk = 0; kk < 16; kk++) {
            float4 wa = *(const float4*)&wsm[kk][o0];
            float4 wb = *(const float4*)&wsm[kk][o0 + 4];
            float4 f4 = *(const float4*)&fsm[kk][mg * 4];
            float wv[8] = {wa.x, wa.y, wa.z, wa.w, wb.x, wb.y, wb.z, wb.w};
            float fv[4] = {f4.x, f4.y, f4.z, f4.w};
#pragma unroll
            for (int q = 0; q < 8; q++)
#pragma unroll
                for (int s = 0; s < 4; s++) acc[q][s] += wv[q] * fv[s];
        }
        __syncthreads();
    }
#pragma unroll
    for (int s = 0; s < 4; s++) {
        float* dst = &g_part[kz * PARTSTRIDE + (r0 + s) * NOP + o0];
        float4 v1 = make_float4(acc[0][s], acc[1][s], acc[2][s], acc[3][s]);
        float4 v2 = make_float4(acc[4][s], acc[5][s], acc[6][s], acc[7][s]);
        *(float4*)dst = v1;
        *(float4*)(dst + 4) = v2;
    }
}

// ---------------- fused reduce + bias + argmax + final decode ---------------
__global__ void k_head_final(const float* __restrict__ head_b, float* __restrict__ out) {
    __shared__ float ho[NO];
    int roi = blockIdx.x;
    int tid = threadIdx.x;
    if (tid < NO) {
        float s = 0.f;
        for (int z = 0; z < KSPLIT; z++) s += g_part[z * PARTSTRIDE + roi * NOP + tid];
        s += head_b[tid];
        ho[tid] = s;
        if (tid < NCLS) out[OUT_FCLS + roi * NCLS + tid] = s;
        else            out[OUT_FTFM + roi * 84 + (tid - NCLS)] = s;
    }
    __syncthreads();
    if (tid == 0) {
        int det = 0;
        float best = ho[0];
        for (int c = 1; c < NCLS; c++) {
            float v = ho[c];
            if (v > best) { best = v; det = c; }
        }
        float t0 = ho[NCLS + det * 4 + 0];
        float t1 = ho[NCLS + det * 4 + 1];
        float t2 = ho[NCLS + det * 4 + 2];
        float t3 = ho[NCLS + det * 4 + 3];
        float X = g_rois[roi * 4 + 0] * 16.f;
        float Y = g_rois[roi * 4 + 1] * 16.f;
        float Wd = g_rois[roi * 4 + 2] * 16.f;
        float Hd = g_rois[roi * 4 + 3] * 16.f;
        out[OUT_FBOX + roi * 5 + 0] = 0.f;
        out[OUT_FBOX + roi * 5 + 1] = X + Wd * t1;
        out[OUT_FBOX + roi * 5 + 2] = Y + Hd * t0;
        out[OUT_FBOX + roi * 5 + 3] = Wd * expf(t3);
        out[OUT_FBOX + roi * 5 + 4] = Hd * expf(t2);
    }
}

// ---------------- launcher --------------------------------------------------
extern "C" void kernel_launch(void* const* d_in, const int* in_sizes, int n_in,
                              void* d_out, int out_size) {
    const float* x      = (const float*)d_in[0];
    const float* rpn_w  = (const float*)d_in[1];
    const float* rpn_b  = (const float*)d_in[2];
    const float* cls_w  = (const float*)d_in[3];
    const float* cls_b  = (const float*)d_in[4];
    const float* tfm_w  = (const float*)d_in[5];
    const float* tfm_b  = (const float*)d_in[6];
    const float* head_w = (const float*)d_in[7];
    const float* head_b = (const float*)d_in[8];
    const float* anchors = (const float*)d_in[9];
    float* out = (float*)d_out;

    k_prep<<<(NWT + NWR + 1023) / 1024, 1024>>>(rpn_w, cls_w, tfm_w);

    k_conv3x3<<<dim3(4, 8, 8), 256>>>(x, rpn_b);
    k_rpn_heads<<<128, 256>>>(cls_b, tfm_b, out);

    k_decode_sort<<<32, 1024>>>(out, anchors);
    k_merge4<<<8, 1024>>>(0);     // g_key (32 runs) -> g_key2 (8 runs)
    k_merge4<<<2, 1024>>>(1);     // g_key2 (8 runs) -> g_key (2 runs)
    k_final_merge<<<1, 1024>>>(); // g_key (2 runs) -> boxes

    k_iou_build<<<125, 512>>>();
    k_nms_scan<<<1, 1024>>>(out);

    k_roi_align<<<dim3(KPOST, 8), 256>>>(x);
    k_head_gemm<<<dim3(4, KSPLIT), 224>>>(head_w);
    k_head_final<<<KPOST, 128>>>(head_b, out);
}